// round 15
// baseline (speedup 1.0000x reference)
#include <cuda_runtime.h>
#include <cuda_bf16.h>
#include <math.h>
#include <stdint.h>

#define N_NODES 50000
#define N_EDGES 800000
#define IN_F    256
#define OUT_F   64
#define HEADS   4
#define HO      256
#define NEG_SLOPE 0.2f

#define SCAN_BLK 256
#define NSCAN ((N_NODES + SCAN_BLK - 1) / SCAN_BLK)   // 196

// ---------------- scratch (static device globals) --------------------------
__device__ float g_h[(size_t)N_NODES * HO];        // 51.2 MB projected features
__device__ float g_attn_src[N_NODES * HEADS];
__device__ float g_attn_dst[N_NODES * HEADS];
__device__ float g_e[(size_t)N_EDGES * HEADS];     // scores by edge id (seq)
__device__ int   g_max_bits;
__device__ int   g_deg[N_NODES];
__device__ int   g_scan[N_NODES];
__device__ int   g_bsum[NSCAN];
__device__ int   g_rowstart[N_NODES];
__device__ int   g_ptr[N_NODES];
__device__ int2  g_sorted[N_EDGES];                // (src, eid) combined
// bf16-split B images in mma-ready padded layout: [8 chunks][256 n][20 words]
__device__ uint32_t g_Bhi[8 * 256 * 20];
__device__ uint32_t g_Blo[8 * 256 * 20];

// ---------------- helpers ----------------------------------------------------
__device__ __forceinline__ uint32_t smem_u32(const void* p) {
    uint32_t a;
    asm("{ .reg .u64 t; cvta.to.shared.u64 t, %1; cvt.u32.u64 %0, t; }" : "=r"(a) : "l"(p));
    return a;
}
__device__ __forceinline__ uint32_t pack2(float a, float b) {
    __nv_bfloat162 h = __floats2bfloat162_rn(a, b);
    return *(uint32_t*)&h;
}
__device__ __forceinline__ void split2(float v, float& hi, float& lo) {
    hi = __bfloat162float(__float2bfloat16(v));
    lo = v - hi;
}
__device__ __forceinline__ void ldm4(uint32_t& r0, uint32_t& r1, uint32_t& r2, uint32_t& r3,
                                     uint32_t addr) {
    asm volatile("ldmatrix.sync.aligned.m8n8.x4.shared.b16 {%0,%1,%2,%3}, [%4];"
                 : "=r"(r0), "=r"(r1), "=r"(r2), "=r"(r3) : "r"(addr));
}
__device__ __forceinline__ void mma16816(float* c, const uint32_t* a, const uint32_t* b) {
    asm("mma.sync.aligned.m16n8k16.row.col.f32.bf16.bf16.f32 "
        "{%0,%1,%2,%3},{%4,%5,%6,%7},{%8,%9},{%0,%1,%2,%3};"
        : "+f"(c[0]), "+f"(c[1]), "+f"(c[2]), "+f"(c[3])
        : "r"(a[0]), "r"(a[1]), "r"(a[2]), "r"(a[3]), "r"(b[0]), "r"(b[1]));
}

// ---------------- kernel: init + precompute split B images (merged) ---------
// Wc[k][n] = W[n>>6][k][n&63]; layout: [chunk c][n][20 words], word kp packs k=2kp,2kp+1
__global__ void init_prep_kernel(const float* __restrict__ W) {
    int tid = blockIdx.x * blockDim.x + threadIdx.x;   // NSCAN*256 = 50176
    if (tid == 0) g_max_bits = 0xFF800000;             // -inf
    if (tid < N_NODES) {
        g_deg[tid] = 0;
        *(float4*)(g_attn_src + tid * 4) = make_float4(0.f, 0.f, 0.f, 0.f);
        *(float4*)(g_attn_dst + tid * 4) = make_float4(0.f, 0.f, 0.f, 0.f);
    }
    if (tid < 32768) {
        int c  = tid >> 12;
        int r  = tid & 4095;
        int n  = r >> 4;
        int kp = r & 15;
        int k0 = c * 32 + kp * 2;
        const float* Wn = W + (size_t)(n >> 6) * IN_F * OUT_F + (n & 63);
        float v0 = Wn[(size_t)k0 * OUT_F];
        float v1 = Wn[(size_t)(k0 + 1) * OUT_F];
        float h0, l0, h1, l1;
        split2(v0, h0, l0);
        split2(v1, h1, l1);
        int w = (c * 256 + n) * 20 + kp;
        g_Bhi[w] = pack2(h0, h1);
        g_Blo[w] = pack2(l0, l1);
    }
}

// ---------------- GEMM: mma.sync bf16, 2-way split, 3 products --------------
// CTA tile 128m x 128n, K-chunks of 32; 8 warps = 2(M) x 4(N), warp 64x32
// Prologue also does the dst histogram; epilogue accumulates attn logits.
#define ASTRIDE_W 20          // words per smem row (80 B)
#define SM_AH 0
#define SM_AL 2560
#define SM_BH 5120
#define SM_BL 7680

__global__ void __launch_bounds__(256) gemm_mma_kernel(const float* __restrict__ x,
                                                       const float* __restrict__ a_src,
                                                       const float* __restrict__ a_dst,
                                                       const int* __restrict__ eidx) {
    __shared__ __align__(16) uint32_t sm[4 * 2560];   // 40 KB
    const int t    = threadIdx.x;
    const int lane = t & 31;
    const int wid  = t >> 5;
    const int m0   = blockIdx.x * 128;
    const int n0   = blockIdx.y * 128;
    const int mw   = (wid >> 2) * 64;   // warp M offset in tile
    const int nw   = (wid & 3) * 32;    // warp N offset in tile
    const uint32_t sb = smem_u32(sm);

    // ---- fused dst histogram (grid-strided) ----
    {
        int nthreads = gridDim.x * gridDim.y * 256;
        int gtid = ((blockIdx.y * gridDim.x + blockIdx.x) * 256) + t;
        for (int e = gtid; e < N_EDGES; e += nthreads)
            atomicAdd(&g_deg[__ldg(&eidx[N_EDGES + e])], 1);
    }

    float acc[4][4][4] = {};

    const uint32_t a_row  = (uint32_t)(lane & 15);
    const uint32_t a_colb = (uint32_t)((lane >> 4) << 4);          // 0 or 16
    const uint32_t b_row  = (uint32_t)((lane & 7) + ((lane & 16) ? 8 : 0));
    const uint32_t b_colb = (uint32_t)((lane & 8) ? 16 : 0);

    for (int c = 0; c < 8; c++) {
        // ---- A fill: 128 rows x 32 k, fp32 -> bf16 hi/lo ----
        #pragma unroll
        for (int it = 0; it < 4; it++) {
            int f   = t + 256 * it;      // 0..1023 float4s
            int row = f >> 3;
            int kq  = f & 7;
            float4 v = make_float4(0.f, 0.f, 0.f, 0.f);
            if (m0 + row < N_NODES)
                v = *(const float4*)(x + (size_t)(m0 + row) * IN_F + c * 32 + kq * 4);
            float hx, lx, hy, ly, hz, lz, hw, lw;
            split2(v.x, hx, lx); split2(v.y, hy, ly);
            split2(v.z, hz, lz); split2(v.w, hw, lw);
            int off = row * ASTRIDE_W + kq * 2;
            *(uint2*)(sm + SM_AH + off) = make_uint2(pack2(hx, hy), pack2(hz, hw));
            *(uint2*)(sm + SM_AL + off) = make_uint2(pack2(lx, ly), pack2(lz, lw));
        }
        // ---- B fill: copy padded global images ----
        #pragma unroll
        for (int it = 0; it < 2; it++) {
            int idx = t + 256 * it;      // 0..511
            int row = idx >> 2;
            int q   = idx & 3;
            int soff = row * ASTRIDE_W + q * 4;
            int goff = (c * 256 + n0 + row) * 20 + q * 4;
            *(uint4*)(sm + SM_BH + soff) = *(const uint4*)(g_Bhi + goff);
            *(uint4*)(sm + SM_BL + soff) = *(const uint4*)(g_Blo + goff);
        }
        __syncthreads();

        // ---- compute: 2 k16-steps ----
        #pragma unroll
        for (int ks = 0; ks < 2; ks++) {
            uint32_t ah[4][4], al[4][4];
            #pragma unroll
            for (int i = 0; i < 4; i++) {
                uint32_t aoff = (mw + i * 16 + a_row) * 80 + ks * 32 + a_colb;
                ldm4(ah[i][0], ah[i][1], ah[i][2], ah[i][3], sb + SM_AH * 4 + aoff);
                ldm4(al[i][0], al[i][1], al[i][2], al[i][3], sb + SM_AL * 4 + aoff);
            }
            uint32_t bh[4][2], bl[4][2];
            #pragma unroll
            for (int j2 = 0; j2 < 2; j2++) {
                uint32_t boff = (nw + j2 * 16 + b_row) * 80 + ks * 32 + b_colb;
                ldm4(bh[2 * j2][0], bh[2 * j2][1], bh[2 * j2 + 1][0], bh[2 * j2 + 1][1],
                     sb + SM_BH * 4 + boff);
                ldm4(bl[2 * j2][0], bl[2 * j2][1], bl[2 * j2 + 1][0], bl[2 * j2 + 1][1],
                     sb + SM_BL * 4 + boff);
            }
            #pragma unroll
            for (int i = 0; i < 4; i++)
                #pragma unroll
                for (int j = 0; j < 4; j++) {
                    mma16816(acc[i][j], ah[i], bh[j]);
                    mma16816(acc[i][j], ah[i], bl[j]);
                    mma16816(acc[i][j], al[i], bh[j]);
                }
        }
        __syncthreads();
    }

    // ---- epilogue: store h ----
    #pragma unroll
    for (int i = 0; i < 4; i++) {
        int row = m0 + mw + i * 16 + (lane >> 2);
        #pragma unroll
        for (int j = 0; j < 4; j++) {
            int col = n0 + nw + j * 8 + (lane & 3) * 2;
            if (row < N_NODES)
                *(float2*)(g_h + (size_t)row * HO + col) = make_float2(acc[i][j][0], acc[i][j][1]);
            if (row + 8 < N_NODES)
                *(float2*)(g_h + (size_t)(row + 8) * HO + col) = make_float2(acc[i][j][2], acc[i][j][3]);
        }
    }

    // ---- fused attn logits ----
    float avs[8], avd[8];
    #pragma unroll
    for (int j = 0; j < 4; j++) {
        int col = n0 + nw + j * 8 + (lane & 3) * 2;
        avs[j * 2]     = __ldg(a_src + col);
        avs[j * 2 + 1] = __ldg(a_src + col + 1);
        avd[j * 2]     = __ldg(a_dst + col);
        avd[j * 2 + 1] = __ldg(a_dst + col + 1);
    }
    const int h_idx = (n0 + nw) >> 6;   // this warp's 32 cols lie in one head
    #pragma unroll
    for (int i = 0; i < 4; i++) {
        float slo = 0.f, shi = 0.f, dlo = 0.f, dhi = 0.f;
        #pragma unroll
        for (int j = 0; j < 4; j++) {
            slo = fmaf(acc[i][j][0], avs[j * 2], fmaf(acc[i][j][1], avs[j * 2 + 1], slo));
            shi = fmaf(acc[i][j][2], avs[j * 2], fmaf(acc[i][j][3], avs[j * 2 + 1], shi));
            dlo = fmaf(acc[i][j][0], avd[j * 2], fmaf(acc[i][j][1], avd[j * 2 + 1], dlo));
            dhi = fmaf(acc[i][j][2], avd[j * 2], fmaf(acc[i][j][3], avd[j * 2 + 1], dhi));
        }
        #pragma unroll
        for (int o = 1; o <= 2; o <<= 1) {
            slo += __shfl_xor_sync(0xFFFFFFFFu, slo, o);
            shi += __shfl_xor_sync(0xFFFFFFFFu, shi, o);
            dlo += __shfl_xor_sync(0xFFFFFFFFu, dlo, o);
            dhi += __shfl_xor_sync(0xFFFFFFFFu, dhi, o);
        }
        if ((lane & 3) == 0) {
            int r1 = m0 + mw + i * 16 + (lane >> 2);
            if (r1 < N_NODES) {
                atomicAdd(&g_attn_src[r1 * 4 + h_idx], slo);
                atomicAdd(&g_attn_dst[r1 * 4 + h_idx], dlo);
            }
            if (r1 + 8 < N_NODES) {
                atomicAdd(&g_attn_src[(r1 + 8) * 4 + h_idx], shi);
                atomicAdd(&g_attn_dst[(r1 + 8) * 4 + h_idx], dhi);
            }
        }
    }
}

// ---------------- scan kernels (proven R2) -----------------------------------
__global__ void scan1_kernel() {
    __shared__ int s[SCAN_BLK];
    int t = threadIdx.x;
    int i = blockIdx.x * SCAN_BLK + t;
    int v = (i < N_NODES) ? g_deg[i] : 0;
    s[t] = v;
    __syncthreads();
    #pragma unroll
    for (int off = 1; off < SCAN_BLK; off <<= 1) {
        int tmp = (t >= off) ? s[t - off] : 0;
        __syncthreads();
        if (t >= off) s[t] += tmp;
        __syncthreads();
    }
    if (i < N_NODES) g_scan[i] = s[t];
    if (t == SCAN_BLK - 1) g_bsum[blockIdx.x] = s[t];
}
__global__ void scan2_kernel() {
    __shared__ int s[SCAN_BLK];
    int t = threadIdx.x;
    int v = (t < NSCAN) ? g_bsum[t] : 0;
    s[t] = v;
    __syncthreads();
    #pragma unroll
    for (int off = 1; off < SCAN_BLK; off <<= 1) {
        int tmp = (t >= off) ? s[t - off] : 0;
        __syncthreads();
        if (t >= off) s[t] += tmp;
        __syncthreads();
    }
    if (t < NSCAN) g_bsum[t] = s[t] - v;
}
__global__ void scan3_kernel() {
    int i = blockIdx.x * SCAN_BLK + threadIdx.x;
    if (i < N_NODES) {
        int rs = g_scan[i] - g_deg[i] + g_bsum[blockIdx.x];
        g_rowstart[i] = rs;
        g_ptr[i] = rs;
    }
}

// ---------------- kernel: scores + int2 bucket + max, 2-edge unroll ---------
__device__ __forceinline__ float leaky(float v) { return v >= 0.0f ? v : NEG_SLOPE * v; }

__device__ void atomic_max_float(int* addr, float value) {
    int old = *addr;
    while (__int_as_float(old) < value) {
        int assumed = old;
        old = atomicCAS(addr, assumed, __float_as_int(value));
        if (old == assumed) break;
    }
}

__global__ void score_sort_kernel(const int* __restrict__ ei,
                                  const float* __restrict__ ew) {
    int base = (blockIdx.x * blockDim.x + threadIdx.x) * 2;
    float local = -INFINITY;
    if (base < N_EDGES) {
        int e0 = base;
        int e1 = base + 1;                 // always < N_EDGES (N_EDGES even)
        // issue all index loads first
        int src0 = __ldg(&ei[e0]);
        int src1 = __ldg(&ei[e1]);
        int dst0 = __ldg(&ei[N_EDGES + e0]);
        int dst1 = __ldg(&ei[N_EDGES + e1]);
        float w0 = __ldg(&ew[e0]);
        float w1 = __ldg(&ew[e1]);
        // then all gathers
        float4 as0 = *(const float4*)(g_attn_src + src0 * 4);
        float4 as1 = *(const float4*)(g_attn_src + src1 * 4);
        float4 ad0 = *(const float4*)(g_attn_dst + dst0 * 4);
        float4 ad1 = *(const float4*)(g_attn_dst + dst1 * 4);

        float4 r0, r1;
        r0.x = leaky(as0.x + ad0.x) * w0;
        r0.y = leaky(as0.y + ad0.y) * w0;
        r0.z = leaky(as0.z + ad0.z) * w0;
        r0.w = leaky(as0.w + ad0.w) * w0;
        r1.x = leaky(as1.x + ad1.x) * w1;
        r1.y = leaky(as1.y + ad1.y) * w1;
        r1.z = leaky(as1.z + ad1.z) * w1;
        r1.w = leaky(as1.w + ad1.w) * w1;
        *(float4*)(g_e + (size_t)e0 * 4) = r0;    // sequential 16B writes
        *(float4*)(g_e + (size_t)e1 * 4) = r1;
        int p0 = atomicAdd(&g_ptr[dst0], 1);
        g_sorted[p0] = make_int2(src0, e0);       // 8B scatters
        int p1 = atomicAdd(&g_ptr[dst1], 1);
        g_sorted[p1] = make_int2(src1, e1);
        local = fmaxf(fmaxf(fmaxf(r0.x, r0.y), fmaxf(r0.z, r0.w)),
                      fmaxf(fmaxf(r1.x, r1.y), fmaxf(r1.z, r1.w)));
    }
    #pragma unroll
    for (int o = 16; o; o >>= 1)
        local = fmaxf(local, __shfl_xor_sync(0xFFFFFFFFu, local, o));
    if ((threadIdx.x & 31) == 0 && local > -INFINITY)
        atomic_max_float(&g_max_bits, local);
}

// ---------------- kernel: gather-aggregate, 1 warp/node, 2-edge unroll ------
__global__ void __launch_bounds__(64) aggregate_kernel(float* __restrict__ out) {
    int n    = (blockIdx.x * blockDim.x + threadIdx.x) >> 5;
    int lane = threadIdx.x & 31;
    if (n >= N_NODES) return;

    const int start = g_rowstart[n];
    const int deg   = g_deg[n];
    const float m   = __int_as_float(g_max_bits);

    float4 acc0 = make_float4(0.f, 0.f, 0.f, 0.f);
    float4 acc1 = make_float4(0.f, 0.f, 0.f, 0.f);
    float4 ds   = make_float4(0.f, 0.f, 0.f, 0.f);

    int i = 0;
    for (; i + 2 <= deg; i += 2) {
        // issue ALL loads for both edges before consuming either
        int2 sa = __ldg(&g_sorted[start + i]);
        int2 sb = __ldg(&g_sorted[start + i + 1]);
        float4 sc0 = *(const float4*)(g_e + (size_t)sa.y * 4);
        float4 sc1 = *(const float4*)(g_e + (size_t)sb.y * 4);
        const float4* ha = (const float4*)(g_h + (size_t)sa.x * HO);
        const float4* hb = (const float4*)(g_h + (size_t)sb.x * HO);
        float4 va0 = ha[lane];
        float4 va1 = ha[lane + 32];
        float4 vb0 = hb[lane];
        float4 vb1 = hb[lane + 32];

        float4 e0, e1;
        e0.x = __expf(sc0.x - m); e0.y = __expf(sc0.y - m);
        e0.z = __expf(sc0.z - m); e0.w = __expf(sc0.w - m);
        e1.x = __expf(sc1.x - m); e1.y = __expf(sc1.y - m);
        e1.z = __expf(sc1.z - m); e1.w = __expf(sc1.w - m);
        ds.x += e0.x + e1.x; ds.y += e0.y + e1.y;
        ds.z += e0.z + e1.z; ds.w += e0.w + e1.w;

        float a0lo = (lane < 16) ? e0.x : e0.y;
        float a0hi = (lane < 16) ? e0.z : e0.w;
        float a1lo = (lane < 16) ? e1.x : e1.y;
        float a1hi = (lane < 16) ? e1.z : e1.w;
        acc0.x = fmaf(va0.x, a0lo, fmaf(vb0.x, a1lo, acc0.x));
        acc0.y = fmaf(va0.y, a0lo, fmaf(vb0.y, a1lo, acc0.y));
        acc0.z = fmaf(va0.z, a0lo, fmaf(vb0.z, a1lo, acc0.z));
        acc0.w = fmaf(va0.w, a0lo, fmaf(vb0.w, a1lo, acc0.w));
        acc1.x = fmaf(va1.x, a0hi, fmaf(vb1.x, a1hi, acc1.x));
        acc1.y = fmaf(va1.y, a0hi, fmaf(vb1.y, a1hi, acc1.y));
        acc1.z = fmaf(va1.z, a0hi, fmaf(vb1.z, a1hi, acc1.z));
        acc1.w = fmaf(va1.w, a0hi, fmaf(vb1.w, a1hi, acc1.w));
    }
    if (i < deg) {
        int2 sa = __ldg(&g_sorted[start + i]);
        float4 sc = *(const float4*)(g_e + (size_t)sa.y * 4);
        const float4* ha = (const float4*)(g_h + (size_t)sa.x * HO);
        float4 v0 = ha[lane];
        float4 v1 = ha[lane + 32];
        float4 ee;
        ee.x = __expf(sc.x - m); ee.y = __expf(sc.y - m);
        ee.z = __expf(sc.z - m); ee.w = __expf(sc.w - m);
        ds.x += ee.x; ds.y += ee.y; ds.z += ee.z; ds.w += ee.w;
        float alo = (lane < 16) ? ee.x : ee.y;
        float ahi = (lane < 16) ? ee.z : ee.w;
        acc0.x = fmaf(v0.x, alo, acc0.x);
        acc0.y = fmaf(v0.y, alo, acc0.y);
        acc0.z = fmaf(v0.z, alo, acc0.z);
        acc0.w = fmaf(v0.w, alo, acc0.w);
        acc1.x = fmaf(v1.x, ahi, acc1.x);
        acc1.y = fmaf(v1.y, ahi, acc1.y);
        acc1.z = fmaf(v1.z, ahi, acc1.z);
        acc1.w = fmaf(v1.w, ahi, acc1.w);
    }

    float dlo = 1.0f / (((lane < 16) ? ds.x : ds.y) + 1e-10f);
    float dhi = 1.0f / (((lane < 16) ? ds.z : ds.w) + 1e-10f);
    float4* od = (float4*)(out + (size_t)n * HO);
    od[lane]      = make_float4(acc0.x * dlo, acc0.y * dlo, acc0.z * dlo, acc0.w * dlo);
    od[lane + 32] = make_float4(acc1.x * dhi, acc1.y * dhi, acc1.z * dhi, acc1.w * dhi);
}

// ---------------- launch ------------------------------------------------------
extern "C" void kernel_launch(void* const* d_in, const int* in_sizes, int n_in,
                              void* d_out, int out_size) {
    const float* x     = (const float*)d_in[0];
    const int*   eidx  = (const int*)  d_in[1];
    const float* ew    = (const float*)d_in[2];
    const float* W     = (const float*)d_in[3];
    const float* a_src = (const float*)d_in[4];
    const float* a_dst = (const float*)d_in[5];
    float* out = (float*)d_out;

    init_prep_kernel<<<NSCAN, SCAN_BLK>>>(W);

    dim3 ggrid((N_NODES + 127) / 128, 2);
    gemm_mma_kernel<<<ggrid, 256>>>(x, a_src, a_dst, eidx);

    scan1_kernel<<<NSCAN, SCAN_BLK>>>();
    scan2_kernel<<<1, SCAN_BLK>>>();
    scan3_kernel<<<NSCAN, SCAN_BLK>>>();

    score_sort_kernel<<<(N_EDGES / 2 + 255) / 256, 256>>>(eidx, ew);

    aggregate_kernel<<<(N_NODES * 32 + 63) / 64, 64>>>(out);
}

// round 17
// speedup vs baseline: 1.0037x; 1.0037x over previous
#include <cuda_runtime.h>
#include <cuda_bf16.h>
#include <math.h>
#include <stdint.h>

#define N_NODES 50000
#define N_EDGES 800000
#define IN_F    256
#define OUT_F   64
#define HEADS   4
#define HO      256
#define NEG_SLOPE 0.2f

#define SCAN_BLK 256
#define NSCAN ((N_NODES + SCAN_BLK - 1) / SCAN_BLK)   // 196

// ---------------- scratch (static device globals) --------------------------
__device__ float g_h[(size_t)N_NODES * HO];        // 51.2 MB projected features
__device__ float g_attn_src[N_NODES * HEADS];
__device__ float g_attn_dst[N_NODES * HEADS];
__device__ int   g_max_bits;                       // EXACT edge-score max
__device__ int   g_deg[N_NODES];
__device__ int   g_scan[N_NODES];
__device__ int   g_bsum[NSCAN];
__device__ int   g_rowstart[N_NODES];
__device__ int   g_ptr[N_NODES];
__device__ int2  g_sorted[N_EDGES];                // (src, ew_bits) combined
// bf16-split B images in mma-ready padded layout: [8 chunks][256 n][20 words]
__device__ uint32_t g_Bhi[8 * 256 * 20];
__device__ uint32_t g_Blo[8 * 256 * 20];

// ---------------- helpers ----------------------------------------------------
__device__ __forceinline__ uint32_t smem_u32(const void* p) {
    uint32_t a;
    asm("{ .reg .u64 t; cvta.to.shared.u64 t, %1; cvt.u32.u64 %0, t; }" : "=r"(a) : "l"(p));
    return a;
}
__device__ __forceinline__ uint32_t pack2(float a, float b) {
    __nv_bfloat162 h = __floats2bfloat162_rn(a, b);
    return *(uint32_t*)&h;
}
__device__ __forceinline__ void split2(float v, float& hi, float& lo) {
    hi = __bfloat162float(__float2bfloat16(v));
    lo = v - hi;
}
__device__ __forceinline__ void ldm4(uint32_t& r0, uint32_t& r1, uint32_t& r2, uint32_t& r3,
                                     uint32_t addr) {
    asm volatile("ldmatrix.sync.aligned.m8n8.x4.shared.b16 {%0,%1,%2,%3}, [%4];"
                 : "=r"(r0), "=r"(r1), "=r"(r2), "=r"(r3) : "r"(addr));
}
__device__ __forceinline__ void mma16816(float* c, const uint32_t* a, const uint32_t* b) {
    asm("mma.sync.aligned.m16n8k16.row.col.f32.bf16.bf16.f32 "
        "{%0,%1,%2,%3},{%4,%5,%6,%7},{%8,%9},{%0,%1,%2,%3};"
        : "+f"(c[0]), "+f"(c[1]), "+f"(c[2]), "+f"(c[3])
        : "r"(a[0]), "r"(a[1]), "r"(a[2]), "r"(a[3]), "r"(b[0]), "r"(b[1]));
}
__device__ __forceinline__ float leaky(float v) { return v >= 0.0f ? v : NEG_SLOPE * v; }

__device__ void atomic_max_float(int* addr, float value) {
    int old = *addr;
    while (__int_as_float(old) < value) {
        int assumed = old;
        old = atomicCAS(addr, assumed, __float_as_int(value));
        if (old == assumed) break;
    }
}

// ---------------- kernel: init + precompute split B images (merged) ---------
__global__ void init_prep_kernel(const float* __restrict__ W) {
    int tid = blockIdx.x * blockDim.x + threadIdx.x;   // NSCAN*256 = 50176
    if (tid == 0) g_max_bits = 0xFF800000;             // -inf
    if (tid < N_NODES) {
        g_deg[tid] = 0;
        *(float4*)(g_attn_src + tid * 4) = make_float4(0.f, 0.f, 0.f, 0.f);
        *(float4*)(g_attn_dst + tid * 4) = make_float4(0.f, 0.f, 0.f, 0.f);
    }
    if (tid < 32768) {
        int c  = tid >> 12;
        int r  = tid & 4095;
        int n  = r >> 4;
        int kp = r & 15;
        int k0 = c * 32 + kp * 2;
        const float* Wn = W + (size_t)(n >> 6) * IN_F * OUT_F + (n & 63);
        float v0 = Wn[(size_t)k0 * OUT_F];
        float v1 = Wn[(size_t)(k0 + 1) * OUT_F];
        float h0, l0, h1, l1;
        split2(v0, h0, l0);
        split2(v1, h1, l1);
        int w = (c * 256 + n) * 20 + kp;
        g_Bhi[w] = pack2(h0, h1);
        g_Blo[w] = pack2(l0, l1);
    }
}

// ---------------- GEMM: mma.sync bf16, 2-way split, 3 products --------------
// CTA tile 128m x 128n; prologue dst-histogram; epilogue attn logits.
#define ASTRIDE_W 20          // words per smem row (80 B)
#define SM_AH 0
#define SM_AL 2560
#define SM_BH 5120
#define SM_BL 7680

__global__ void __launch_bounds__(256) gemm_mma_kernel(const float* __restrict__ x,
                                                       const float* __restrict__ a_src,
                                                       const float* __restrict__ a_dst,
                                                       const int* __restrict__ eidx) {
    __shared__ __align__(16) uint32_t sm[4 * 2560];   // 40 KB
    const int t    = threadIdx.x;
    const int lane = t & 31;
    const int wid  = t >> 5;
    const int m0   = blockIdx.x * 128;
    const int n0   = blockIdx.y * 128;
    const int mw   = (wid >> 2) * 64;
    const int nw   = (wid & 3) * 32;
    const uint32_t sb = smem_u32(sm);

    // ---- fused dst histogram (grid-strided) ----
    {
        int nthreads = gridDim.x * gridDim.y * 256;
        int gtid = ((blockIdx.y * gridDim.x + blockIdx.x) * 256) + t;
        for (int e = gtid; e < N_EDGES; e += nthreads)
            atomicAdd(&g_deg[__ldg(&eidx[N_EDGES + e])], 1);
    }

    float acc[4][4][4] = {};

    const uint32_t a_row  = (uint32_t)(lane & 15);
    const uint32_t a_colb = (uint32_t)((lane >> 4) << 4);
    const uint32_t b_row  = (uint32_t)((lane & 7) + ((lane & 16) ? 8 : 0));
    const uint32_t b_colb = (uint32_t)((lane & 8) ? 16 : 0);

    for (int c = 0; c < 8; c++) {
        #pragma unroll
        for (int it = 0; it < 4; it++) {
            int f   = t + 256 * it;
            int row = f >> 3;
            int kq  = f & 7;
            float4 v = make_float4(0.f, 0.f, 0.f, 0.f);
            if (m0 + row < N_NODES)
                v = *(const float4*)(x + (size_t)(m0 + row) * IN_F + c * 32 + kq * 4);
            float hx, lx, hy, ly, hz, lz, hw, lw;
            split2(v.x, hx, lx); split2(v.y, hy, ly);
            split2(v.z, hz, lz); split2(v.w, hw, lw);
            int off = row * ASTRIDE_W + kq * 2;
            *(uint2*)(sm + SM_AH + off) = make_uint2(pack2(hx, hy), pack2(hz, hw));
            *(uint2*)(sm + SM_AL + off) = make_uint2(pack2(lx, ly), pack2(lz, lw));
        }
        #pragma unroll
        for (int it = 0; it < 2; it++) {
            int idx = t + 256 * it;
            int row = idx >> 2;
            int q   = idx & 3;
            int soff = row * ASTRIDE_W + q * 4;
            int goff = (c * 256 + n0 + row) * 20 + q * 4;
            *(uint4*)(sm + SM_BH + soff) = *(const uint4*)(g_Bhi + goff);
            *(uint4*)(sm + SM_BL + soff) = *(const uint4*)(g_Blo + goff);
        }
        __syncthreads();

        #pragma unroll
        for (int ks = 0; ks < 2; ks++) {
            uint32_t ah[4][4], al[4][4];
            #pragma unroll
            for (int i = 0; i < 4; i++) {
                uint32_t aoff = (mw + i * 16 + a_row) * 80 + ks * 32 + a_colb;
                ldm4(ah[i][0], ah[i][1], ah[i][2], ah[i][3], sb + SM_AH * 4 + aoff);
                ldm4(al[i][0], al[i][1], al[i][2], al[i][3], sb + SM_AL * 4 + aoff);
            }
            uint32_t bh[4][2], bl[4][2];
            #pragma unroll
            for (int j2 = 0; j2 < 2; j2++) {
                uint32_t boff = (nw + j2 * 16 + b_row) * 80 + ks * 32 + b_colb;
                ldm4(bh[2 * j2][0], bh[2 * j2][1], bh[2 * j2 + 1][0], bh[2 * j2 + 1][1],
                     sb + SM_BH * 4 + boff);
                ldm4(bl[2 * j2][0], bl[2 * j2][1], bl[2 * j2 + 1][0], bl[2 * j2 + 1][1],
                     sb + SM_BL * 4 + boff);
            }
            #pragma unroll
            for (int i = 0; i < 4; i++)
                #pragma unroll
                for (int j = 0; j < 4; j++) {
                    mma16816(acc[i][j], ah[i], bh[j]);
                    mma16816(acc[i][j], ah[i], bl[j]);
                    mma16816(acc[i][j], al[i], bh[j]);
                }
        }
        __syncthreads();
    }

    // ---- epilogue: store h ----
    #pragma unroll
    for (int i = 0; i < 4; i++) {
        int row = m0 + mw + i * 16 + (lane >> 2);
        #pragma unroll
        for (int j = 0; j < 4; j++) {
            int col = n0 + nw + j * 8 + (lane & 3) * 2;
            if (row < N_NODES)
                *(float2*)(g_h + (size_t)row * HO + col) = make_float2(acc[i][j][0], acc[i][j][1]);
            if (row + 8 < N_NODES)
                *(float2*)(g_h + (size_t)(row + 8) * HO + col) = make_float2(acc[i][j][2], acc[i][j][3]);
        }
    }

    // ---- fused attn logits ----
    float avs[8], avd[8];
    #pragma unroll
    for (int j = 0; j < 4; j++) {
        int col = n0 + nw + j * 8 + (lane & 3) * 2;
        avs[j * 2]     = __ldg(a_src + col);
        avs[j * 2 + 1] = __ldg(a_src + col + 1);
        avd[j * 2]     = __ldg(a_dst + col);
        avd[j * 2 + 1] = __ldg(a_dst + col + 1);
    }
    const int h_idx = (n0 + nw) >> 6;
    #pragma unroll
    for (int i = 0; i < 4; i++) {
        float slo = 0.f, shi = 0.f, dlo = 0.f, dhi = 0.f;
        #pragma unroll
        for (int j = 0; j < 4; j++) {
            slo = fmaf(acc[i][j][0], avs[j * 2], fmaf(acc[i][j][1], avs[j * 2 + 1], slo));
            shi = fmaf(acc[i][j][2], avs[j * 2], fmaf(acc[i][j][3], avs[j * 2 + 1], shi));
            dlo = fmaf(acc[i][j][0], avd[j * 2], fmaf(acc[i][j][1], avd[j * 2 + 1], dlo));
            dhi = fmaf(acc[i][j][2], avd[j * 2], fmaf(acc[i][j][3], avd[j * 2 + 1], dhi));
        }
        #pragma unroll
        for (int o = 1; o <= 2; o <<= 1) {
            slo += __shfl_xor_sync(0xFFFFFFFFu, slo, o);
            shi += __shfl_xor_sync(0xFFFFFFFFu, shi, o);
            dlo += __shfl_xor_sync(0xFFFFFFFFu, dlo, o);
            dhi += __shfl_xor_sync(0xFFFFFFFFu, dhi, o);
        }
        if ((lane & 3) == 0) {
            int r1 = m0 + mw + i * 16 + (lane >> 2);
            if (r1 < N_NODES) {
                atomicAdd(&g_attn_src[r1 * 4 + h_idx], slo);
                atomicAdd(&g_attn_dst[r1 * 4 + h_idx], dlo);
            }
            if (r1 + 8 < N_NODES) {
                atomicAdd(&g_attn_src[(r1 + 8) * 4 + h_idx], shi);
                atomicAdd(&g_attn_dst[(r1 + 8) * 4 + h_idx], dhi);
            }
        }
    }
}

// ---------------- scan kernels (proven R2) -----------------------------------
__global__ void scan1_kernel() {
    __shared__ int s[SCAN_BLK];
    int t = threadIdx.x;
    int i = blockIdx.x * SCAN_BLK + t;
    int v = (i < N_NODES) ? g_deg[i] : 0;
    s[t] = v;
    __syncthreads();
    #pragma unroll
    for (int off = 1; off < SCAN_BLK; off <<= 1) {
        int tmp = (t >= off) ? s[t - off] : 0;
        __syncthreads();
        if (t >= off) s[t] += tmp;
        __syncthreads();
    }
    if (i < N_NODES) g_scan[i] = s[t];
    if (t == SCAN_BLK - 1) g_bsum[blockIdx.x] = s[t];
}
__global__ void scan2_kernel() {
    __shared__ int s[SCAN_BLK];
    int t = threadIdx.x;
    int v = (t < NSCAN) ? g_bsum[t] : 0;
    s[t] = v;
    __syncthreads();
    #pragma unroll
    for (int off = 1; off < SCAN_BLK; off <<= 1) {
        int tmp = (t >= off) ? s[t - off] : 0;
        __syncthreads();
        if (t >= off) s[t] += tmp;
        __syncthreads();
    }
    if (t < NSCAN) g_bsum[t] = s[t] - v;
}
__global__ void scan3_kernel() {
    int i = blockIdx.x * SCAN_BLK + threadIdx.x;
    if (i < N_NODES) {
        int rs = g_scan[i] - g_deg[i] + g_bsum[blockIdx.x];
        g_rowstart[i] = rs;
        g_ptr[i] = rs;
    }
}

// ---------------- kernel: bucket edges + EXACT score max (no score write) ---
__global__ void sort_max_kernel(const int* __restrict__ ei,
                                const float* __restrict__ ew) {
    int e = blockIdx.x * blockDim.x + threadIdx.x;
    float local = -INFINITY;
    if (e < N_EDGES) {
        int src = __ldg(&ei[e]);
        int dst = __ldg(&ei[N_EDGES + e]);
        float w = __ldg(&ew[e]);
        float4 as = *(const float4*)(g_attn_src + src * 4);
        float4 ad = *(const float4*)(g_attn_dst + dst * 4);
        float4 r;
        r.x = leaky(as.x + ad.x) * w;
        r.y = leaky(as.y + ad.y) * w;
        r.z = leaky(as.z + ad.z) * w;
        r.w = leaky(as.w + ad.w) * w;
        local = fmaxf(fmaxf(r.x, r.y), fmaxf(r.z, r.w));
        int pos = atomicAdd(&g_ptr[dst], 1);
        g_sorted[pos] = make_int2(src, __float_as_int(w));   // single 8B scatter
    }
    #pragma unroll
    for (int o = 16; o; o >>= 1)
        local = fmaxf(local, __shfl_xor_sync(0xFFFFFFFFu, local, o));
    if ((threadIdx.x & 31) == 0 && local > -INFINITY)
        atomic_max_float(&g_max_bits, local);
}

// ---------------- kernel: gather-aggregate with inline scores ----------------
__global__ void __launch_bounds__(64) aggregate_kernel(float* __restrict__ out) {
    int n    = (blockIdx.x * blockDim.x + threadIdx.x) >> 5;
    int lane = threadIdx.x & 31;
    if (n >= N_NODES) return;

    const int start = g_rowstart[n];
    const int deg   = g_deg[n];
    const float m   = __int_as_float(g_max_bits);
    const float4 ad = *(const float4*)(g_attn_dst + n * 4);   // once per warp

    float4 acc0 = make_float4(0.f, 0.f, 0.f, 0.f);
    float4 acc1 = make_float4(0.f, 0.f, 0.f, 0.f);
    float4 ds   = make_float4(0.f, 0.f, 0.f, 0.f);

    int i = 0;
    for (; i + 2 <= deg; i += 2) {
        // issue ALL loads for both edges before consuming either
        int2 sa = __ldg(&g_sorted[start + i]);
        int2 sb = __ldg(&g_sorted[start + i + 1]);
        float4 as0 = *(const float4*)(g_attn_src + sa.x * 4);
        float4 as1 = *(const float4*)(g_attn_src + sb.x * 4);
        const float4* ha = (const float4*)(g_h + (size_t)sa.x * HO);
        const float4* hb = (const float4*)(g_h + (size_t)sb.x * HO);
        float4 va0 = ha[lane];
        float4 va1 = ha[lane + 32];
        float4 vb0 = hb[lane];
        float4 vb1 = hb[lane + 32];
        float wa = __int_as_float(sa.y);
        float wb = __int_as_float(sb.y);

        float4 e0, e1;
        e0.x = __expf(leaky(as0.x + ad.x) * wa - m);
        e0.y = __expf(leaky(as0.y + ad.y) * wa - m);
        e0.z = __expf(leaky(as0.z + ad.z) * wa - m);
        e0.w = __expf(leaky(as0.w + ad.w) * wa - m);
        e1.x = __expf(leaky(as1.x + ad.x) * wb - m);
        e1.y = __expf(leaky(as1.y + ad.y) * wb - m);
        e1.z = __expf(leaky(as1.z + ad.z) * wb - m);
        e1.w = __expf(leaky(as1.w + ad.w) * wb - m);
        ds.x += e0.x + e1.x; ds.y += e0.y + e1.y;
        ds.z += e0.z + e1.z; ds.w += e0.w + e1.w;

        float a0lo = (lane < 16) ? e0.x : e0.y;
        float a0hi = (lane < 16) ? e0.z : e0.w;
        float a1lo = (lane < 16) ? e1.x : e1.y;
        float a1hi = (lane < 16) ? e1.z : e1.w;
        acc0.x = fmaf(va0.x, a0lo, fmaf(vb0.x, a1lo, acc0.x));
        acc0.y = fmaf(va0.y, a0lo, fmaf(vb0.y, a1lo, acc0.y));
        acc0.z = fmaf(va0.z, a0lo, fmaf(vb0.z, a1lo, acc0.z));
        acc0.w = fmaf(va0.w, a0lo, fmaf(vb0.w, a1lo, acc0.w));
        acc1.x = fmaf(va1.x, a0hi, fmaf(vb1.x, a1hi, acc1.x));
        acc1.y = fmaf(va1.y, a0hi, fmaf(vb1.y, a1hi, acc1.y));
        acc1.z = fmaf(va1.z, a0hi, fmaf(vb1.z, a1hi, acc1.z));
        acc1.w = fmaf(va1.w, a0hi, fmaf(vb1.w, a1hi, acc1.w));
    }
    if (i < deg) {
        int2 sa = __ldg(&g_sorted[start + i]);
        float4 as0 = *(const float4*)(g_attn_src + sa.x * 4);
        const float4* ha = (const float4*)(g_h + (size_t)sa.x * HO);
        float4 v0 = ha[lane];
        float4 v1 = ha[lane + 32];
        float wa = __int_as_float(sa.y);
        float4 ee;
        ee.x = __expf(leaky(as0.x + ad.x) * wa - m);
        ee.y = __expf(leaky(as0.y + ad.y) * wa - m);
        ee.z = __expf(leaky(as0.z + ad.z) * wa - m);
        ee.w = __expf(leaky(as0.w + ad.w) * wa - m);
        ds.x += ee.x; ds.y += ee.y; ds.z += ee.z; ds.w += ee.w;
        float alo = (lane < 16) ? ee.x : ee.y;
        float ahi = (lane < 16) ? ee.z : ee.w;
        acc0.x = fmaf(v0.x, alo, acc0.x);
        acc0.y = fmaf(v0.y, alo, acc0.y);
        acc0.z = fmaf(v0.z, alo, acc0.z);
        acc0.w = fmaf(v0.w, alo, acc0.w);
        acc1.x = fmaf(v1.x, ahi, acc1.x);
        acc1.y = fmaf(v1.y, ahi, acc1.y);
        acc1.z = fmaf(v1.z, ahi, acc1.z);
        acc1.w = fmaf(v1.w, ahi, acc1.w);
    }

    float dlo = 1.0f / (((lane < 16) ? ds.x : ds.y) + 1e-10f);
    float dhi = 1.0f / (((lane < 16) ? ds.z : ds.w) + 1e-10f);
    float4* od = (float4*)(out + (size_t)n * HO);
    od[lane]      = make_float4(acc0.x * dlo, acc0.y * dlo, acc0.z * dlo, acc0.w * dlo);
    od[lane + 32] = make_float4(acc1.x * dhi, acc1.y * dhi, acc1.z * dhi, acc1.w * dhi);
}

// ---------------- launch ------------------------------------------------------
extern "C" void kernel_launch(void* const* d_in, const int* in_sizes, int n_in,
                              void* d_out, int out_size) {
    const float* x     = (const float*)d_in[0];
    const int*   eidx  = (const int*)  d_in[1];
    const float* ew    = (const float*)d_in[2];
    const float* W     = (const float*)d_in[3];
    const float* a_src = (const float*)d_in[4];
    const float* a_dst = (const float*)d_in[5];
    float* out = (float*)d_out;

    init_prep_kernel<<<NSCAN, SCAN_BLK>>>(W);

    dim3 ggrid((N_NODES + 127) / 128, 2);
    gemm_mma_kernel<<<ggrid, 256>>>(x, a_src, a_dst, eidx);

    scan1_kernel<<<NSCAN, SCAN_BLK>>>();
    scan2_kernel<<<1, SCAN_BLK>>>();
    scan3_kernel<<<NSCAN, SCAN_BLK>>>();

    sort_max_kernel<<<(N_EDGES + 255) / 256, 256>>>(eidx, ew);

    aggregate_kernel<<<(N_NODES * 32 + 63) / 64, 64>>>(out);
}